// round 6
// baseline (speedup 1.0000x reference)
#include <cuda_runtime.h>

#define NXC 128
#define NYC 128
#define NZC 64
#define BC  2
#define TC  12

constexpr int MCELL = NXC * NYC * NZC;   // 1,048,576
constexpr int NCELL = BC * MCELL;        // 2,097,152
constexpr int M4  = MCELL / 4;
constexpr int F4  = NCELL / 4;           // float4 stride between fields
constexpr int SX4 = NYC * NZC / 4;       // 2048
constexpr int SY4 = NZC / 4;             // 16

constexpr int XR  = 8;                   // x rows per block
constexpr int YT  = 16;                  // owned y rows per block

constexpr float DTc   = 1e-3f;
constexpr float INVH  = 0.1f;
constexpr float BULK  = 1.0f - 0.01f * 1e-3f;
constexpr float H     = 10.0f;
constexpr float SRC_Z = 320.0f;
constexpr float IS_XY = 1.0f / 800.0f;
constexpr float IS_Z  = 1.0f / 200.0f;

// Ping-pong state: slot x {vx,vy,vz} and slot x {sxx,syy,szz,sxy,sxz,syz}.
__device__ float g_v[2][3][NCELL];
__device__ float g_s[2][6][NCELL];

// ---- float4 helpers -------------------------------------------------------
__device__ __forceinline__ float4 operator+(float4 a, float4 b) {
    return make_float4(a.x + b.x, a.y + b.y, a.z + b.z, a.w + b.w);
}
__device__ __forceinline__ float4 operator-(float4 a, float4 b) {
    return make_float4(a.x - b.x, a.y - b.y, a.z - b.z, a.w - b.w);
}
__device__ __forceinline__ float4 operator*(float s, float4 a) {
    return make_float4(s * a.x, s * a.y, s * a.z, s * a.w);
}
__device__ __forceinline__ float4 operator*(float4 a, float4 b) {
    return make_float4(a.x * b.x, a.y * b.y, a.z * b.z, a.w * b.w);
}

__device__ __forceinline__ float4 shift_fwd(float4 v, int k4, unsigned m) {
    float n = __shfl_down_sync(m, v.x, 1, 16);
    if (k4 == 15) n = v.w;
    return make_float4(v.y, v.z, v.w, n);
}
__device__ __forceinline__ float4 shift_bwd(float4 v, int k4, unsigned m) {
    float p = __shfl_up_sync(m, v.w, 1, 16);
    if (k4 == 0) p = v.x;
    return make_float4(p, v.x, v.y, v.z);
}

// ---- init: slot 0 gets vz = source injection; nothing else is ever read ---
__global__ __launch_bounds__(256) void init_step_kernel(
    const float* __restrict__ rho, const float* __restrict__ damping,
    const float* __restrict__ traj)
{
    const int k4 = threadIdx.x;
    const int j  = blockIdx.x * 16 + threadIdx.y;
    const int i  = blockIdx.y;
    const int b  = blockIdx.z;
    const int mm4  = (i * NYC + j) * SY4 + k4;
    const int idx4 = b * M4 + mm4;

    const float xt = traj[(b * TC + 0) * 2 + 0];
    const float yt = traj[(b * TC + 0) * 2 + 1];
    const float xg = (i + 0.5f) * H, yg = (j + 0.5f) * H;
    const float axy = -((xg - xt) * (xg - xt) + (yg - yt) * (yg - yt)) * IS_XY;
    float s[4];
    #pragma unroll
    for (int c = 0; c < 4; c++) {
        float dz = (4 * k4 + c + 0.5f) * H - SRC_Z;
        float arg = axy - dz * dz * IS_Z;
        s[c] = (arg > -60.0f) ? __expf(arg) : 0.0f;
    }
    const float rinv = 1.0f / rho[0];
    const float4 damp = reinterpret_cast<const float4*>(damping)[mm4];
    const float4 fac = BULK * damp;
    reinterpret_cast<float4*>(g_v[0][2])[idx4] =
        ((DTc * rinv) * make_float4(s[0], s[1], s[2], s[3])) * fac;
}

// ---- fused stress+velocity step, x-marching, ping-pong buffers ------------
// Block: (16 z4, 17 y-rows); ty=0 is the y-halo stress row (j0-1).
// Reads only slot rd; writes only slot rd^1  ->  race-free across blocks.
template <bool FIRST>
__global__ __launch_bounds__(272, 2) void fused_step_kernel(
    const float* __restrict__ rho, const float* __restrict__ damping,
    const float* __restrict__ traj,
    const float* __restrict__ lam, const float* __restrict__ mu,
    const float* __restrict__ eta,
    int t, int rd, int write_out, float* __restrict__ out)
{
    const int k4 = threadIdx.x;                // 0..15
    const int ty = threadIdx.y;                // 0..16
    const int xs = blockIdx.x * XR;
    const int j0 = blockIdx.y * YT;
    const int b  = blockIdx.z;
    const int j  = j0 - 1 + ty;
    const int jc = (j >= 0) ? j : 0;
    const bool vel_row = (ty >= 1);
    const unsigned wmask = (ty == 16) ? 0x0000ffffu : 0xffffffffu;
    const float4 Z0 = make_float4(0.f, 0.f, 0.f, 0.f);

    __shared__ float4 s_vx[17][16], s_vy[17][16], s_vz[17][16];
    __shared__ float4 s_sxy[17][16], s_syy[17][16], s_syz[17][16];

    // Prologue (input-only work, overlapped with previous grid via PDL).
    const float lam0 = lam[0];
    const float mu0  = mu[0];
    const float me   = mu0 + eta[0];
    const float rinv = 1.0f / rho[0];
    const float xt = traj[(b * TC + t) * 2 + 0];
    const float yt = traj[(b * TC + t) * 2 + 1];
    float zsq[4];
    #pragma unroll
    for (int c = 0; c < 4; c++) {
        float dz = (4 * k4 + c + 0.5f) * H - SRC_Z;
        zsq[c] = dz * dz;
    }
    const float dy2 = ((j + 0.5f) * H - yt) * ((j + 0.5f) * H - yt);

    cudaGridDependencySynchronize();

    // Slot base pointers (field f at constant offset f*F4).
    const float4* Vr = reinterpret_cast<const float4*>(g_v[rd]);
    const float4* Sr = reinterpret_cast<const float4*>(g_s[rd]);
    float4* Vw = reinterpret_cast<float4*>(g_v[rd ^ 1]);
    float4* Sw = reinterpret_cast<float4*>(g_s[rd ^ 1]);

    const int x0 = (xs == 0) ? 0 : xs - 1;

    // Preload old velocity at x0.
    int id = b * M4 + (x0 * NYC + jc) * SY4 + k4;
    float4 vxC = FIRST ? Z0 : Vr[0 * F4 + id];
    float4 vyC = FIRST ? Z0 : Vr[1 * F4 + id];
    float4 vzC = Vr[2 * F4 + id];

    float4 sxxP = Z0, sxyP = Z0, sxzP = Z0;   // carried x-1 new stress

    for (int x = x0; x < xs + XR; ++x) {
        id = b * M4 + (x * NYC + jc) * SY4 + k4;
        const bool hx = (x + 1 < NXC);
        const int idn = hx ? id + SX4 : id;

        // Front-batched independent loads.
        const float4 vxN = FIRST ? Z0 : Vr[0 * F4 + idn];
        const float4 vyN = FIRST ? Z0 : Vr[1 * F4 + idn];
        const float4 vzN = Vr[2 * F4 + idn];
        const float4 oxx = FIRST ? Z0 : Sr[0 * F4 + id];
        const float4 oyy = FIRST ? Z0 : Sr[1 * F4 + id];
        const float4 ozz = FIRST ? Z0 : Sr[2 * F4 + id];
        const float4 oxy = FIRST ? Z0 : Sr[3 * F4 + id];
        const float4 oxz = FIRST ? Z0 : Sr[4 * F4 + id];
        const float4 oyz = FIRST ? Z0 : Sr[5 * F4 + id];
        const float4 damp = reinterpret_cast<const float4*>(damping)
                                [(x * NYC + jc) * SY4 + k4];

        // Exchange old velocity across y.
        s_vx[ty][k4] = vxC; s_vy[ty][k4] = vyC; s_vz[ty][k4] = vzC;
        __syncthreads();
        float4 vxY, vyY, vzY;
        if (ty < 16) {
            vxY = s_vx[ty + 1][k4];
            vyY = s_vy[ty + 1][k4];
            vzY = s_vz[ty + 1][k4];
        } else if (j0 + YT < NYC) {
            vxY = FIRST ? Z0 : Vr[0 * F4 + id + SY4];
            vyY = FIRST ? Z0 : Vr[1 * F4 + id + SY4];
            vzY = Vr[2 * F4 + id + SY4];
        } else {
            vxY = vxC; vyY = vyC; vzY = vzC;
        }

        // Stress update (all rows compute; halo rows never stored).
        const float4 vx_z = shift_fwd(vxC, k4, wmask);
        const float4 vy_z = shift_fwd(vyC, k4, wmask);
        const float4 vz_z = shift_fwd(vzC, k4, wmask);

        const float4 exx = INVH * (vxN - vxC);
        const float4 eyy = INVH * (vyY - vyC);
        const float4 ezz = INVH * (vz_z - vzC);
        const float4 exy2 = INVH * ((vxY - vxC) + (vyN - vyC));
        const float4 exz2 = INVH * ((vx_z - vxC) + (vzN - vzC));
        const float4 eyz2 = INVH * ((vy_z - vyC) + (vzY - vzC));
        const float4 tr = exx + eyy + ezz;

        const float4 nxx = oxx + DTc * (lam0 * tr + (2.0f * mu0) * exx);
        const float4 nyy = oyy + DTc * (lam0 * tr + (2.0f * mu0) * eyy);
        const float4 nzz = ozz + DTc * (lam0 * tr + (2.0f * mu0) * ezz);
        const float4 nxy = oxy + (DTc * me) * exy2;
        const float4 nxz = oxz + (DTc * me) * exz2;
        const float4 nyz = oyz + (DTc * me) * eyz2;

        if (x >= xs && vel_row) {
            Sw[0 * F4 + id] = nxx; Sw[1 * F4 + id] = nyy; Sw[2 * F4 + id] = nzz;
            Sw[3 * F4 + id] = nxy; Sw[4 * F4 + id] = nxz; Sw[5 * F4 + id] = nyz;
        }

        s_sxy[ty][k4] = nxy; s_syy[ty][k4] = nyy; s_syz[ty][k4] = nyz;
        __syncthreads();

        // Velocity (z-shifts hoisted out of divergent region).
        const float4 sxz_z = shift_bwd(nxz, k4, wmask);
        const float4 syz_z = shift_bwd(nyz, k4, wmask);
        const float4 szz_z = shift_bwd(nzz, k4, wmask);

        if (x >= xs && vel_row) {
            float4 sxy_y, syy_y, syz_y;
            if (j > 0) {
                sxy_y = s_sxy[ty - 1][k4];
                syy_y = s_syy[ty - 1][k4];
                syz_y = s_syz[ty - 1][k4];
            } else {
                sxy_y = nxy; syy_y = nyy; syz_y = nyz;
            }
            float4 sxx_x, sxy_x, sxz_x;
            if (x > 0) { sxx_x = sxxP; sxy_x = sxyP; sxz_x = sxzP; }
            else       { sxx_x = nxx;  sxy_x = nxy;  sxz_x = nxz; }

            const float4 div_x = INVH * ((nxx - sxx_x) + (nxy - sxy_y) + (nxz - sxz_z));
            const float4 div_y = INVH * ((nxy - sxy_x) + (nyy - syy_y) + (nyz - syz_z));
            const float4 div_z = INVH * ((nxz - sxz_x) + (nyz - syz_y) + (nzz - szz_z));

            const float xg = (x + 0.5f) * H;
            const float axy = -((xg - xt) * (xg - xt) + dy2) * IS_XY;
            float s[4];
            #pragma unroll
            for (int c = 0; c < 4; c++) {
                float arg = axy - zsq[c] * IS_Z;
                s[c] = (arg > -60.0f) ? __expf(arg) : 0.0f;
            }
            const float4 src = make_float4(s[0], s[1], s[2], s[3]);

            const float4 fac = BULK * damp;
            const float4 vxn = (vxC + (DTc * rinv) * div_x) * fac;
            const float4 vyn = (vyC + (DTc * rinv) * div_y) * fac;
            const float4 vzn = (vzC + (DTc * rinv) * (div_z + src)) * fac;

            Vw[0 * F4 + id] = vxn;
            Vw[1 * F4 + id] = vyn;
            Vw[2 * F4 + id] = vzn;

            if (write_out) {
                float4* out4 = reinterpret_cast<float4*>(out);
                out4[id] = vzn;
                float4 sm;
                sm.x = sqrtf(nxy.x * nxy.x + nxz.x * nxz.x + nyz.x * nyz.x + 1e-8f);
                sm.y = sqrtf(nxy.y * nxy.y + nxz.y * nxz.y + nyz.y * nyz.y + 1e-8f);
                sm.z = sqrtf(nxy.z * nxy.z + nxz.z * nxz.z + nyz.z * nyz.z + 1e-8f);
                sm.w = sqrtf(nxy.w * nxy.w + nxz.w * nxz.w + nyz.w * nyz.w + 1e-8f);
                out4[F4 + id] = sm;
            }
        }

        sxxP = nxx; sxyP = nxy; sxzP = nxz;
        vxC = vxN; vyC = vyN; vzC = vzN;
    }
}

// ---- PDL launch helper ----------------------------------------------------
template <typename... Args>
static void launch_pdl(void (*kern)(Args...), dim3 grd, dim3 blk, Args... args)
{
    cudaLaunchAttribute attr[1];
    attr[0].id = cudaLaunchAttributeProgrammaticStreamSerialization;
    attr[0].val.programmaticStreamSerializationAllowed = 1;
    cudaLaunchConfig_t cfg{};
    cfg.gridDim = grd;
    cfg.blockDim = blk;
    cfg.dynamicSmemBytes = 0;
    cfg.stream = 0;
    cfg.attrs = attr;
    cfg.numAttrs = 1;
    cudaLaunchKernelEx(&cfg, kern, args...);
}

extern "C" void kernel_launch(void* const* d_in, const int* in_sizes, int n_in,
                              void* d_out, int out_size)
{
    // metadata order: trajectory, grid_x, grid_y, grid_z, rho, mu, lam, eta, damping
    const float* traj    = (const float*)d_in[0];
    const float* rho     = (const float*)d_in[4];
    const float* mu      = (const float*)d_in[5];
    const float* lam     = (const float*)d_in[6];
    const float* eta     = (const float*)d_in[7];
    const float* damping = (const float*)d_in[8];
    float* out = (float*)d_out;

    dim3 blkI(16, 16, 1);
    dim3 grdI(NYC / 16, NXC, BC);
    init_step_kernel<<<grdI, blkI>>>(rho, damping, traj);

    dim3 blk(16, 17, 1);
    dim3 grd(NXC / XR, NYC / YT, BC);
    for (int t = 1; t < TC; t++) {
        const int rd = (t - 1) & 1;
        const int wo = (t == TC - 1) ? 1 : 0;
        if (t == 1)
            launch_pdl(fused_step_kernel<true>, grd, blk,
                       rho, damping, traj, lam, mu, eta, t, rd, wo, out);
        else
            launch_pdl(fused_step_kernel<false>, grd, blk,
                       rho, damping, traj, lam, mu, eta, t, rd, wo, out);
    }
}

// round 7
// speedup vs baseline: 1.3146x; 1.3146x over previous
#include <cuda_runtime.h>

#define NXC 128
#define NYC 128
#define NZC 64
#define BC  2
#define TC  12

constexpr int MCELL = NXC * NYC * NZC;   // 1,048,576
constexpr int NCELL = BC * MCELL;        // 2,097,152
constexpr int M4  = MCELL / 4;           // float4 cells per batch
constexpr int F4  = NCELL / 4;           // float4 stride between fields
constexpr int SX4 = NYC * NZC / 4;       // 2048
constexpr int SY4 = NZC / 4;             // 16

constexpr float DTc   = 1e-3f;
constexpr float INVH  = 0.1f;
constexpr float BULK  = 1.0f - 0.01f * 1e-3f;
constexpr float H     = 10.0f;
constexpr float SRC_Z = 320.0f;
constexpr float IS_XY = 1.0f / 800.0f;
constexpr float IS_Z  = 1.0f / 200.0f;

// All 9 state fields behind ONE base pointer: field f at offset f*NCELL.
// 0:vx 1:vy 2:vz 3:sxx 4:syy 5:szz 6:sxy 7:sxz 8:syz
__device__ float g_state[9][NCELL];

// ---- float4 helpers -------------------------------------------------------
__device__ __forceinline__ float4 operator+(float4 a, float4 b) {
    return make_float4(a.x + b.x, a.y + b.y, a.z + b.z, a.w + b.w);
}
__device__ __forceinline__ float4 operator-(float4 a, float4 b) {
    return make_float4(a.x - b.x, a.y - b.y, a.z - b.z, a.w - b.w);
}
__device__ __forceinline__ float4 operator*(float s, float4 a) {
    return make_float4(s * a.x, s * a.y, s * a.z, s * a.w);
}
__device__ __forceinline__ float4 operator*(float4 a, float4 b) {
    return make_float4(a.x * b.x, a.y * b.y, a.z * b.z, a.w * b.w);
}

// Forward z-shift: (v.y, v.z, v.w, next.x); clamp at domain top (k4==15).
__device__ __forceinline__ float4 shift_fwd(float4 v, int k4) {
    float n = __shfl_down_sync(0xffffffffu, v.x, 1, 16);
    if (k4 == 15) n = v.w;
    return make_float4(v.y, v.z, v.w, n);
}
// Backward z-shift: (prev.w, v.x, v.y, v.z); clamp at domain bottom (k4==0).
__device__ __forceinline__ float4 shift_bwd(float4 v, int k4) {
    float p = __shfl_up_sync(0xffffffffu, v.w, 1, 16);
    if (k4 == 0) p = v.x;
    return make_float4(p, v.x, v.y, v.z);
}

// ---- t=0: zero state + pure source injection into vz ----------------------
__global__ __launch_bounds__(256) void init_step_kernel(
    const float* __restrict__ rho, const float* __restrict__ damping,
    const float* __restrict__ traj)
{
    const int k4 = threadIdx.x;
    const int j  = blockIdx.x * 16 + threadIdx.y;
    const int i  = blockIdx.y;
    const int b  = blockIdx.z;
    const int mm4  = (i * NYC + j) * SY4 + k4;
    const int idx4 = b * M4 + mm4;

    float4* st = reinterpret_cast<float4*>(g_state);
    const float4 z4 = make_float4(0.f, 0.f, 0.f, 0.f);
    st[0 * F4 + idx4] = z4;           // vx
    st[1 * F4 + idx4] = z4;           // vy
    #pragma unroll
    for (int f = 3; f < 9; f++)       // stresses
        st[f * F4 + idx4] = z4;

    const float xt = traj[(b * TC + 0) * 2 + 0];
    const float yt = traj[(b * TC + 0) * 2 + 1];
    const float xg = (i + 0.5f) * H, yg = (j + 0.5f) * H;
    const float axy = -((xg - xt) * (xg - xt) + (yg - yt) * (yg - yt)) * IS_XY;
    float s[4];
    #pragma unroll
    for (int c = 0; c < 4; c++) {
        float dz = (4 * k4 + c + 0.5f) * H - SRC_Z;
        float arg = axy - dz * dz * IS_Z;
        s[c] = (arg > -60.0f) ? __expf(arg) : 0.0f;
    }
    const float rinv = 1.0f / rho[0];
    const float4 damp = reinterpret_cast<const float4*>(damping)[mm4];
    const float4 fac = BULK * damp;
    st[2 * F4 + idx4] = ((DTc * rinv) * make_float4(s[0], s[1], s[2], s[3])) * fac;
}

// ---- stress update (forward differences) ----------------------------------
__global__ __launch_bounds__(256, 5) void stress_step_kernel(
    const float* __restrict__ lam, const float* __restrict__ mu,
    const float* __restrict__ eta)
{
    const int k4 = threadIdx.x;
    const int j  = blockIdx.x * 16 + threadIdx.y;
    const int i  = blockIdx.y;
    const int b  = blockIdx.z;
    const int idx4 = b * M4 + (i * NYC + j) * SY4 + k4;

    const bool hx = (i + 1 < NXC);
    const bool hy = (j + 1 < NYC);
    const int ix = hx ? idx4 + SX4 : idx4;
    const int iy = hy ? idx4 + SY4 : idx4;

    // Prologue (state-independent).
    const float lam0 = lam[0];
    const float mu0  = mu[0];
    const float me   = mu0 + eta[0];

    cudaGridDependencySynchronize();

    float4* st = reinterpret_cast<float4*>(g_state);

    // Front-batched loads: 9 velocity + 6 old-stress, all off ONE base.
    const float4 vxc  = st[0 * F4 + idx4];
    const float4 vyc  = st[1 * F4 + idx4];
    const float4 vzc  = st[2 * F4 + idx4];
    const float4 vx_x = st[0 * F4 + ix];
    const float4 vy_x = st[1 * F4 + ix];
    const float4 vz_x = st[2 * F4 + ix];
    const float4 vx_y = st[0 * F4 + iy];
    const float4 vy_y = st[1 * F4 + iy];
    const float4 vz_y = st[2 * F4 + iy];
    const float4 sxx_o = st[3 * F4 + idx4];
    const float4 syy_o = st[4 * F4 + idx4];
    const float4 szz_o = st[5 * F4 + idx4];
    const float4 sxy_o = st[6 * F4 + idx4];
    const float4 sxz_o = st[7 * F4 + idx4];
    const float4 syz_o = st[8 * F4 + idx4];

    const float4 vx_z = shift_fwd(vxc, k4);
    const float4 vy_z = shift_fwd(vyc, k4);
    const float4 vz_z = shift_fwd(vzc, k4);

    const float4 exx = INVH * (vx_x - vxc);
    const float4 eyy = INVH * (vy_y - vyc);
    const float4 ezz = INVH * (vz_z - vzc);
    const float4 exy2 = INVH * ((vx_y - vxc) + (vy_x - vyc));
    const float4 exz2 = INVH * ((vx_z - vxc) + (vz_x - vzc));
    const float4 eyz2 = INVH * ((vy_z - vyc) + (vz_y - vzc));
    const float4 tr = exx + eyy + ezz;

    st[3 * F4 + idx4] = sxx_o + DTc * (lam0 * tr + (2.0f * mu0) * exx);
    st[4 * F4 + idx4] = syy_o + DTc * (lam0 * tr + (2.0f * mu0) * eyy);
    st[5 * F4 + idx4] = szz_o + DTc * (lam0 * tr + (2.0f * mu0) * ezz);
    st[6 * F4 + idx4] = sxy_o + (DTc * me) * exy2;
    st[7 * F4 + idx4] = sxz_o + (DTc * me) * exz2;
    st[8 * F4 + idx4] = syz_o + (DTc * me) * eyz2;
}

// ---- velocity update (backward differences) + source ----------------------
__global__ __launch_bounds__(256, 5) void velocity_step_kernel(
    const float* __restrict__ rho, const float* __restrict__ damping,
    const float* __restrict__ traj, int t, int write_out, float* __restrict__ out)
{
    const int k4 = threadIdx.x;
    const int j  = blockIdx.x * 16 + threadIdx.y;
    const int i  = blockIdx.y;
    const int b  = blockIdx.z;
    const int mm4  = (i * NYC + j) * SY4 + k4;
    const int idx4 = b * M4 + mm4;

    const bool lx = (i > 0);
    const bool ly = (j > 0);
    const int ix = lx ? idx4 - SX4 : idx4;
    const int iy = ly ? idx4 - SY4 : idx4;

    // Prologue: source Gaussian, damping, rho — input-only.
    const float xt = traj[(b * TC + t) * 2 + 0];
    const float yt = traj[(b * TC + t) * 2 + 1];
    const float xg = (i + 0.5f) * H, yg = (j + 0.5f) * H;
    const float axy = -((xg - xt) * (xg - xt) + (yg - yt) * (yg - yt)) * IS_XY;
    float s[4];
    #pragma unroll
    for (int c = 0; c < 4; c++) {
        float dz = (4 * k4 + c + 0.5f) * H - SRC_Z;
        float arg = axy - dz * dz * IS_Z;
        s[c] = (arg > -60.0f) ? __expf(arg) : 0.0f;
    }
    const float4 src = make_float4(s[0], s[1], s[2], s[3]);
    const float rinv = 1.0f / rho[0];
    const float4 damp = reinterpret_cast<const float4*>(damping)[mm4];
    const float4 fac = BULK * damp;

    cudaGridDependencySynchronize();

    float4* st = reinterpret_cast<float4*>(g_state);

    const float4 sxxc = st[3 * F4 + idx4];
    const float4 syyc = st[4 * F4 + idx4];
    const float4 szzc = st[5 * F4 + idx4];
    const float4 sxyc = st[6 * F4 + idx4];
    const float4 sxzc = st[7 * F4 + idx4];
    const float4 syzc = st[8 * F4 + idx4];
    const float4 sxx_x = st[3 * F4 + ix];
    const float4 sxy_x = st[6 * F4 + ix];
    const float4 sxz_x = st[7 * F4 + ix];
    const float4 sxy_y = st[6 * F4 + iy];
    const float4 syy_y = st[4 * F4 + iy];
    const float4 syz_y = st[8 * F4 + iy];
    const float4 vx_old = st[0 * F4 + idx4];
    const float4 vy_old = st[1 * F4 + idx4];
    const float4 vz_old = st[2 * F4 + idx4];

    const float4 sxz_z = shift_bwd(sxzc, k4);
    const float4 syz_z = shift_bwd(syzc, k4);
    const float4 szz_z = shift_bwd(szzc, k4);

    const float4 div_x = INVH * ((sxxc - sxx_x) + (sxyc - sxy_y) + (sxzc - sxz_z));
    const float4 div_y = INVH * ((sxyc - sxy_x) + (syyc - syy_y) + (syzc - syz_z));
    const float4 div_z = INVH * ((sxzc - sxz_x) + (syzc - syz_y) + (szzc - szz_z));

    const float4 vx = (vx_old + (DTc * rinv) * div_x) * fac;
    const float4 vy = (vy_old + (DTc * rinv) * div_y) * fac;
    const float4 vz = (vz_old + (DTc * rinv) * (div_z + src)) * fac;

    st[0 * F4 + idx4] = vx;
    st[1 * F4 + idx4] = vy;
    st[2 * F4 + idx4] = vz;

    if (write_out) {
        float4* out4 = reinterpret_cast<float4*>(out);
        out4[idx4] = vz;
        float4 sm;
        sm.x = sqrtf(sxyc.x * sxyc.x + sxzc.x * sxzc.x + syzc.x * syzc.x + 1e-8f);
        sm.y = sqrtf(sxyc.y * sxyc.y + sxzc.y * sxzc.y + syzc.y * syzc.y + 1e-8f);
        sm.z = sqrtf(sxyc.z * sxyc.z + sxzc.z * sxzc.z + syzc.z * syzc.z + 1e-8f);
        sm.w = sqrtf(sxyc.w * sxyc.w + sxzc.w * sxzc.w + syzc.w * syzc.w + 1e-8f);
        out4[F4 + idx4] = sm;
    }
}

// ---- PDL launch helper ----------------------------------------------------
template <typename... Args>
static void launch_pdl(void (*kern)(Args...), dim3 grd, dim3 blk, Args... args)
{
    cudaLaunchAttribute attr[1];
    attr[0].id = cudaLaunchAttributeProgrammaticStreamSerialization;
    attr[0].val.programmaticStreamSerializationAllowed = 1;
    cudaLaunchConfig_t cfg{};
    cfg.gridDim = grd;
    cfg.blockDim = blk;
    cfg.dynamicSmemBytes = 0;
    cfg.stream = 0;
    cfg.attrs = attr;
    cfg.numAttrs = 1;
    cudaLaunchKernelEx(&cfg, kern, args...);
}

extern "C" void kernel_launch(void* const* d_in, const int* in_sizes, int n_in,
                              void* d_out, int out_size)
{
    // metadata order: trajectory, grid_x, grid_y, grid_z, rho, mu, lam, eta, damping
    const float* traj    = (const float*)d_in[0];
    const float* rho     = (const float*)d_in[4];
    const float* mu      = (const float*)d_in[5];
    const float* lam     = (const float*)d_in[6];
    const float* eta     = (const float*)d_in[7];
    const float* damping = (const float*)d_in[8];
    float* out = (float*)d_out;

    dim3 blk(16, 16, 1);
    dim3 grd(NYC / 16, NXC, BC);

    init_step_kernel<<<grd, blk>>>(rho, damping, traj);

    for (int t = 1; t < TC; t++) {
        launch_pdl(stress_step_kernel, grd, blk, lam, mu, eta);
        launch_pdl(velocity_step_kernel, grd, blk, rho, damping, traj, t,
                   (t == TC - 1) ? 1 : 0, out);
    }
}